// round 5
// baseline (speedup 1.0000x reference)
#include <cuda_runtime.h>
#include <cuda_bf16.h>

// PEPS 6x6, D=4, phys=2, batch=1024. Row-sweep exact contraction, snake order.
// One CTA (512 threads) per configuration, single W buffer, 3 CTAs/SM.
// Interior steps: fma.rn.f32x2 packed over n-pairs (A pairs come straight
// from contiguous smem, no duplication movs for A).

#define NT 512

typedef unsigned long long u64;

__device__ __forceinline__ u64 pk(float v) {
    u64 r;
    asm("mov.b64 %0, {%1, %1};" : "=l"(r) : "f"(v));
    return r;
}
__device__ __forceinline__ void fma2(u64& d, u64 a, u64 b) {
    asm("fma.rn.f32x2 %0, %1, %2, %0;" : "+l"(d) : "l"(a), "l"(b));
}
__device__ __forceinline__ float2 upk(u64 v) {
    float2 r;
    asm("mov.b64 {%0, %1}, %2;" : "=f"(r.x), "=f"(r.y) : "l"(v));
    return r;
}

// Generic step (boundary rows), two-phase over the single buffer.
__device__ __forceinline__ void step_generic(
    float* __restrict__ W, const float* __restrict__ A,
    int F, int K, int N, int Pu, int ud, int Srin, int tid)
{
    const int total = N * F;
    float accl[8];
    int cnt = 0;
    for (int o = tid; o < total; o += NT) {
        int n = o / F;
        int m = o - n * F;
        int dp = m / Pu;
        int ur = m - dp * Pu;
        int inb = dp * ud * Pu + ur;
        float s = 0.f;
        for (int k = 0; k < K; ++k) {
            int rin = k / ud;
            int u = k - rin * ud;
            s = fmaf(W[inb + rin * Srin + u * Pu], A[k * N + n], s);
        }
        accl[cnt++] = s;
    }
    __syncthreads();
    cnt = 0;
    for (int o = tid; o < total; o += NT) {
        int n = o / F;
        int m = o - n * F;
        W[n * F + m] = accl[cnt++];
    }
    __syncthreads();
}

// Interior rows, steps 0..4: F=1024, N=16, Pu = 1<<PSH >= 4.
// g = tid>>8 picks 8 n's (4 n-pairs), t = tid&255 picks m-vec 4t..4t+3.
// acc[m-slot(4)][n-pair(4)] packed over n. Per k: 1 LDS.128 input,
// 2 LDS.128 A (gives 4 packed pairs), 4 dup movs, 16 FFMA2.
template <int K, int PSH>
__device__ __forceinline__ void step_fast_vec(
    float* __restrict__ W, const float* __restrict__ A, int tid)
{
    const int g = tid >> 8;           // n-group: n = 8g..8g+7
    const int t = tid & 255;
    const int mb = t << 2;            // m-vec base
    const int dp = mb >> PSH;
    const int ur = mb & ((1 << PSH) - 1);
    const int inb = (dp << (PSH + 2)) + ur;

    u64 acc[4][4];                    // [m-slot][n-pair]
#pragma unroll
    for (int c = 0; c < 4; ++c)
#pragma unroll
        for (int j = 0; j < 4; ++j) acc[c][j] = 0ull;

#pragma unroll
    for (int k = 0; k < K; ++k) {
        const int off = (k >> 2) * 4096 + ((k & 3) << PSH);
        const float4 xv = *(const float4*)(W + inb + off);
        const ulonglong2 a01 = *(const ulonglong2*)(A + k * 16 + g * 8);
        const ulonglong2 a23 = *(const ulonglong2*)(A + k * 16 + g * 8 + 4);
        const u64 ap[4] = { a01.x, a01.y, a23.x, a23.y };
        const u64 xp[4] = { pk(xv.x), pk(xv.y), pk(xv.z), pk(xv.w) };
#pragma unroll
        for (int c = 0; c < 4; ++c)
#pragma unroll
            for (int j = 0; j < 4; ++j)
                fma2(acc[c][j], xp[c], ap[j]);
    }

    __syncthreads();
    // Transpose register tile to [n][m] float4 rows and store.
#pragma unroll
    for (int j = 0; j < 4; ++j) {
        const float2 f0 = upk(acc[0][j]);
        const float2 f1 = upk(acc[1][j]);
        const float2 f2 = upk(acc[2][j]);
        const float2 f3 = upk(acc[3][j]);
        float4 v0, v1;
        v0.x = f0.x; v0.y = f1.x; v0.z = f2.x; v0.w = f3.x;   // n = 8g+2j
        v1.x = f0.y; v1.y = f1.y; v1.z = f2.y; v1.w = f3.y;   // n = 8g+2j+1
        *(float4*)(W + (g * 8 + 2 * j) * 1024 + mb) = v0;
        *(float4*)(W + (g * 8 + 2 * j + 1) * 1024 + mb) = v1;
    }
    __syncthreads();
}

// Interior rows, step 5: F=1024, N=4, K=16 (input layout rin*4096 + m*4 + u).
// 512 threads, 2 m each; acc packed over n-pairs.
__device__ __forceinline__ void step_fast_last(
    float* __restrict__ W, const float* __restrict__ A, int tid)
{
    const int m0 = tid * 2;
    u64 acc[2][2];                    // [m-slot][n-pair]
    acc[0][0] = acc[0][1] = acc[1][0] = acc[1][1] = 0ull;

#pragma unroll
    for (int rin = 0; rin < 4; ++rin) {
        const float4 xv0 = *(const float4*)(W + m0 * 4 + rin * 4096);
        const float4 xv1 = *(const float4*)(W + (m0 + 1) * 4 + rin * 4096);
#pragma unroll
        for (int u = 0; u < 4; ++u) {
            const float x0 = (u == 0) ? xv0.x : (u == 1) ? xv0.y : (u == 2) ? xv0.z : xv0.w;
            const float x1 = (u == 0) ? xv1.x : (u == 1) ? xv1.y : (u == 2) ? xv1.z : xv1.w;
            const ulonglong2 a2 = *(const ulonglong2*)(A + (rin * 4 + u) * 4);
            const u64 p0 = pk(x0);
            const u64 p1 = pk(x1);
            fma2(acc[0][0], p0, a2.x);
            fma2(acc[0][1], p0, a2.y);
            fma2(acc[1][0], p1, a2.x);
            fma2(acc[1][1], p1, a2.y);
        }
    }
    __syncthreads();
#pragma unroll
    for (int p = 0; p < 2; ++p) {
        const float2 v01 = upk(acc[p][0]);
        const float2 v23 = upk(acc[p][1]);
        W[0 * 1024 + m0 + p] = v01.x;
        W[1 * 1024 + m0 + p] = v01.y;
        W[2 * 1024 + m0 + p] = v23.x;
        W[3 * 1024 + m0 + p] = v23.y;
    }
    __syncthreads();
}

__global__ __launch_bounds__(NT, 3)
void peps_amp_kernel(const int* __restrict__ x, const float* __restrict__ T,
                     float* __restrict__ out)
{
    extern __shared__ float smem[];
    float* W = smem;                             // 16384
    float* As = smem + 16384;                    // 6 * 256
    int* spins = (int*)(smem + 16384 + 1536);    // 36 (+ pad)

    const int b = blockIdx.x;
    const int tid = threadIdx.x;

    if (tid < 36) spins[tid] = x[b * 36 + tid];
    if (tid == 0) W[0] = 1.0f;
    __syncthreads();

    for (int i = 0; i < 6; ++i) {
        const int ud = (i == 0) ? 1 : 4;
        const int dd = (i == 5) ? 1 : 4;
        const bool l2r = ((i & 1) == 0);

        // Stage this row's 6 site matrices: As[st][k*N + n],
        // k = rin*ud + u, n = rout*dd + d.
        for (int st = 0; st < 6; ++st) {
            const int Rin  = (st == 0) ? 1 : 4;
            const int Rout = (st == 5) ? 1 : 4;
            const int K = ud * Rin;
            const int N = Rout * dd;
            const int jc = l2r ? st : (5 - st);
            const int s = spins[i * 6 + jc];
            const float* Tb = T + (size_t)((i * 6 + jc) * 2 + s) * 256;
            for (int idx = tid; idx < K * N; idx += NT) {
                int k = idx / N, n = idx - k * N;
                int rin = k / ud, u = k - rin * ud;
                int rout = n / dd, d = n - rout * dd;
                int r = l2r ? rout : rin;
                int l = l2r ? rin : rout;
                As[st * 256 + idx] = Tb[u * 64 + r * 16 + d * 4 + l];
            }
        }
        __syncthreads();

        for (int st = 0; st < 6; ++st) {
            const float* A = As + st * 256;

            if (ud == 4 && dd == 4) {
                switch (st) {
                    case 0: step_fast_vec<4, 10>(W, A, tid); break;
                    case 1: step_fast_vec<16, 8>(W, A, tid); break;
                    case 2: step_fast_vec<16, 6>(W, A, tid); break;
                    case 3: step_fast_vec<16, 4>(W, A, tid); break;
                    case 4: step_fast_vec<16, 2>(W, A, tid); break;
                    default: step_fast_last(W, A, tid); break;
                }
            } else {
                const int Rin  = (st == 0) ? 1 : 4;
                const int Rout = (st == 5) ? 1 : 4;
                const int K = ud * Rin;
                const int N = Rout * dd;
                const int Pd = (dd == 1) ? 1 : (1 << (2 * st));
                const int Pu = (ud == 1) ? 1 : (1 << (2 * (5 - st)));
                step_generic(W, A, Pd * Pu, K, N, Pu, ud,
                             Pd * ud * Pu, tid);
            }
        }
    }

    if (tid == 0) out[b] = W[0];
}

extern "C" void kernel_launch(void* const* d_in, const int* in_sizes, int n_in,
                              void* d_out, int out_size)
{
    const int T_ELEMS = 6 * 6 * 2 * 4 * 4 * 4 * 4;   // 73728
    const int* x;
    const float* T;
    if (in_sizes[0] == T_ELEMS) {
        T = (const float*)d_in[0];
        x = (const int*)d_in[1];
    } else {
        x = (const int*)d_in[0];
        T = (const float*)d_in[1];
    }

    const int smem_bytes = (16384 + 1536 + 64) * (int)sizeof(float);
    cudaFuncSetAttribute(peps_amp_kernel,
                         cudaFuncAttributeMaxDynamicSharedMemorySize, smem_bytes);
    cudaFuncSetAttribute(peps_amp_kernel,
                         cudaFuncAttributePreferredSharedMemoryCarveout, 100);

    peps_amp_kernel<<<out_size, NT, smem_bytes>>>(x, T, (float*)d_out);
}

// round 6
// speedup vs baseline: 1.4988x; 1.4988x over previous
#include <cuda_runtime.h>
#include <cuda_bf16.h>

// PEPS 6x6, D=4, phys=2, batch=1024. Row-sweep exact contraction, snake order.
// One CTA (512 threads) per configuration, single W buffer, 2 CTAs/SM
// (3 CTAs/SM forces 40 regs -> spills the accumulator tile: never again).
// Interior steps: fma.rn.f32x2 packed over n-pairs (A pairs read directly
// from contiguous smem; only the x operand needs dup movs).

#define NT 512

typedef unsigned long long u64;

__device__ __forceinline__ u64 pk(float v) {
    u64 r;
    asm("mov.b64 %0, {%1, %1};" : "=l"(r) : "f"(v));
    return r;
}
__device__ __forceinline__ void fma2(u64& d, u64 a, u64 b) {
    asm("fma.rn.f32x2 %0, %1, %2, %0;" : "+l"(d) : "l"(a), "l"(b));
}
__device__ __forceinline__ float2 upk(u64 v) {
    float2 r;
    asm("mov.b64 {%0, %1}, %2;" : "=f"(r.x), "=f"(r.y) : "l"(v));
    return r;
}

// Generic step (boundary rows), two-phase over the single buffer.
__device__ __forceinline__ void step_generic(
    float* __restrict__ W, const float* __restrict__ A,
    int F, int K, int N, int Pu, int ud, int Srin, int tid)
{
    const int total = N * F;
    float accl[8];
    int cnt = 0;
    for (int o = tid; o < total; o += NT) {
        int n = o / F;
        int m = o - n * F;
        int dp = m / Pu;
        int ur = m - dp * Pu;
        int inb = dp * ud * Pu + ur;
        float s = 0.f;
        for (int k = 0; k < K; ++k) {
            int rin = k / ud;
            int u = k - rin * ud;
            s = fmaf(W[inb + rin * Srin + u * Pu], A[k * N + n], s);
        }
        accl[cnt++] = s;
    }
    __syncthreads();
    cnt = 0;
    for (int o = tid; o < total; o += NT) {
        int n = o / F;
        int m = o - n * F;
        W[n * F + m] = accl[cnt++];
    }
    __syncthreads();
}

// Interior rows, steps 0..4: F=1024, N=16, Pu = 1<<PSH >= 4.
// g = tid>>8 picks 8 n's (4 n-pairs), t = tid&255 picks m-vec 4t..4t+3.
// acc[m-slot(4)][n-pair(4)] packed over n. Per k: 1 LDS.128 input,
// 2 LDS.128 A (4 ready packed pairs), 4 dup movs, 16 FFMA2.
template <int K, int PSH>
__device__ __forceinline__ void step_fast_vec(
    float* __restrict__ W, const float* __restrict__ A, int tid)
{
    const int g = tid >> 8;           // n-group: n = 8g..8g+7
    const int t = tid & 255;
    const int mb = t << 2;            // m-vec base
    const int dp = mb >> PSH;
    const int ur = mb & ((1 << PSH) - 1);
    const int inb = (dp << (PSH + 2)) + ur;

    u64 acc[4][4];                    // [m-slot][n-pair]
#pragma unroll
    for (int c = 0; c < 4; ++c)
#pragma unroll
        for (int j = 0; j < 4; ++j) acc[c][j] = 0ull;

#pragma unroll
    for (int k = 0; k < K; ++k) {
        const int off = (k >> 2) * 4096 + ((k & 3) << PSH);
        const float4 xv = *(const float4*)(W + inb + off);
        const ulonglong2 a01 = *(const ulonglong2*)(A + k * 16 + g * 8);
        const ulonglong2 a23 = *(const ulonglong2*)(A + k * 16 + g * 8 + 4);
        const u64 ap[4] = { a01.x, a01.y, a23.x, a23.y };
        const u64 xp[4] = { pk(xv.x), pk(xv.y), pk(xv.z), pk(xv.w) };
#pragma unroll
        for (int c = 0; c < 4; ++c)
#pragma unroll
            for (int j = 0; j < 4; ++j)
                fma2(acc[c][j], xp[c], ap[j]);
    }

    __syncthreads();
    // Transpose register tile to [n][m] float4 rows and store.
#pragma unroll
    for (int j = 0; j < 4; ++j) {
        const float2 f0 = upk(acc[0][j]);
        const float2 f1 = upk(acc[1][j]);
        const float2 f2 = upk(acc[2][j]);
        const float2 f3 = upk(acc[3][j]);
        float4 v0, v1;
        v0.x = f0.x; v0.y = f1.x; v0.z = f2.x; v0.w = f3.x;   // n = 8g+2j
        v1.x = f0.y; v1.y = f1.y; v1.z = f2.y; v1.w = f3.y;   // n = 8g+2j+1
        *(float4*)(W + (g * 8 + 2 * j) * 1024 + mb) = v0;
        *(float4*)(W + (g * 8 + 2 * j + 1) * 1024 + mb) = v1;
    }
    __syncthreads();
}

// Interior rows, step 5: F=1024, N=4, K=16 (input layout rin*4096 + m*4 + u).
// 512 threads, 2 m each; acc packed over n-pairs.
__device__ __forceinline__ void step_fast_last(
    float* __restrict__ W, const float* __restrict__ A, int tid)
{
    const int m0 = tid * 2;
    u64 acc[2][2];                    // [m-slot][n-pair]
    acc[0][0] = acc[0][1] = acc[1][0] = acc[1][1] = 0ull;

#pragma unroll
    for (int rin = 0; rin < 4; ++rin) {
        const float4 xv0 = *(const float4*)(W + m0 * 4 + rin * 4096);
        const float4 xv1 = *(const float4*)(W + (m0 + 1) * 4 + rin * 4096);
#pragma unroll
        for (int u = 0; u < 4; ++u) {
            const float x0 = (u == 0) ? xv0.x : (u == 1) ? xv0.y : (u == 2) ? xv0.z : xv0.w;
            const float x1 = (u == 0) ? xv1.x : (u == 1) ? xv1.y : (u == 2) ? xv1.z : xv1.w;
            const ulonglong2 a2 = *(const ulonglong2*)(A + (rin * 4 + u) * 4);
            const u64 p0 = pk(x0);
            const u64 p1 = pk(x1);
            fma2(acc[0][0], p0, a2.x);
            fma2(acc[0][1], p0, a2.y);
            fma2(acc[1][0], p1, a2.x);
            fma2(acc[1][1], p1, a2.y);
        }
    }
    __syncthreads();
#pragma unroll
    for (int p = 0; p < 2; ++p) {
        const float2 v01 = upk(acc[p][0]);
        const float2 v23 = upk(acc[p][1]);
        W[0 * 1024 + m0 + p] = v01.x;
        W[1 * 1024 + m0 + p] = v01.y;
        W[2 * 1024 + m0 + p] = v23.x;
        W[3 * 1024 + m0 + p] = v23.y;
    }
    __syncthreads();
}

__global__ __launch_bounds__(NT, 2)
void peps_amp_kernel(const int* __restrict__ x, const float* __restrict__ T,
                     float* __restrict__ out)
{
    extern __shared__ float smem[];
    float* W = smem;                             // 16384
    float* As = smem + 16384;                    // 6 * 256
    int* spins = (int*)(smem + 16384 + 1536);    // 36 (+ pad)

    const int b = blockIdx.x;
    const int tid = threadIdx.x;

    if (tid < 36) spins[tid] = x[b * 36 + tid];
    if (tid == 0) W[0] = 1.0f;
    __syncthreads();

    for (int i = 0; i < 6; ++i) {
        const int ud = (i == 0) ? 1 : 4;
        const int dd = (i == 5) ? 1 : 4;
        const bool l2r = ((i & 1) == 0);

        // Stage this row's 6 site matrices: As[st][k*N + n],
        // k = rin*ud + u, n = rout*dd + d.
        for (int st = 0; st < 6; ++st) {
            const int Rin  = (st == 0) ? 1 : 4;
            const int Rout = (st == 5) ? 1 : 4;
            const int K = ud * Rin;
            const int N = Rout * dd;
            const int jc = l2r ? st : (5 - st);
            const int s = spins[i * 6 + jc];
            const float* Tb = T + (size_t)((i * 6 + jc) * 2 + s) * 256;
            for (int idx = tid; idx < K * N; idx += NT) {
                int k = idx / N, n = idx - k * N;
                int rin = k / ud, u = k - rin * ud;
                int rout = n / dd, d = n - rout * dd;
                int r = l2r ? rout : rin;
                int l = l2r ? rin : rout;
                As[st * 256 + idx] = Tb[u * 64 + r * 16 + d * 4 + l];
            }
        }
        __syncthreads();

        for (int st = 0; st < 6; ++st) {
            const float* A = As + st * 256;

            if (ud == 4 && dd == 4) {
                switch (st) {
                    case 0: step_fast_vec<4, 10>(W, A, tid); break;
                    case 1: step_fast_vec<16, 8>(W, A, tid); break;
                    case 2: step_fast_vec<16, 6>(W, A, tid); break;
                    case 3: step_fast_vec<16, 4>(W, A, tid); break;
                    case 4: step_fast_vec<16, 2>(W, A, tid); break;
                    default: step_fast_last(W, A, tid); break;
                }
            } else {
                const int Rin  = (st == 0) ? 1 : 4;
                const int Rout = (st == 5) ? 1 : 4;
                const int K = ud * Rin;
                const int N = Rout * dd;
                const int Pd = (dd == 1) ? 1 : (1 << (2 * st));
                const int Pu = (ud == 1) ? 1 : (1 << (2 * (5 - st)));
                step_generic(W, A, Pd * Pu, K, N, Pu, ud,
                             Pd * ud * Pu, tid);
            }
        }
    }

    if (tid == 0) out[b] = W[0];
}

extern "C" void kernel_launch(void* const* d_in, const int* in_sizes, int n_in,
                              void* d_out, int out_size)
{
    const int T_ELEMS = 6 * 6 * 2 * 4 * 4 * 4 * 4;   // 73728
    const int* x;
    const float* T;
    if (in_sizes[0] == T_ELEMS) {
        T = (const float*)d_in[0];
        x = (const int*)d_in[1];
    } else {
        x = (const int*)d_in[0];
        T = (const float*)d_in[1];
    }

    const int smem_bytes = (16384 + 1536 + 64) * (int)sizeof(float);
    cudaFuncSetAttribute(peps_amp_kernel,
                         cudaFuncAttributeMaxDynamicSharedMemorySize, smem_bytes);
    cudaFuncSetAttribute(peps_amp_kernel,
                         cudaFuncAttributePreferredSharedMemoryCarveout, 100);

    peps_amp_kernel<<<out_size, NT, smem_bytes>>>(x, T, (float*)d_out);
}

// round 7
// speedup vs baseline: 2.1122x; 1.4093x over previous
#include <cuda_runtime.h>
#include <cuda_bf16.h>

// PEPS 6x6, D=4, phys=2, batch=1024. Row-sweep exact contraction, snake order.
// One CTA (512 threads) per configuration, single W buffer, 2 CTAs/SM.
// Interior steps: fma.rn.f32x2 with acc packed over m-pairs (x pairs come
// naturally from LDS.128); A pre-DUPLICATED in smem as (a,a) u64 pairs so the
// hot loop has ZERO mov instructions: per k = 5 LDS.128 + 16 FFMA2.

#define NT 512

typedef unsigned long long u64;

__device__ __forceinline__ u64 pk(float v) {
    u64 r;
    asm("mov.b64 %0, {%1, %1};" : "=l"(r) : "f"(v));
    return r;
}
__device__ __forceinline__ void fma2(u64& d, u64 a, u64 b) {
    asm("fma.rn.f32x2 %0, %1, %2, %0;" : "+l"(d) : "l"(a), "l"(b));
}
__device__ __forceinline__ float2 upk(u64 v) {
    float2 r;
    asm("mov.b64 {%0, %1}, %2;" : "=f"(r.x), "=f"(r.y) : "l"(v));
    return r;
}

// Generic step (boundary rows), two-phase over the single buffer.
__device__ __forceinline__ void step_generic(
    float* __restrict__ W, const float* __restrict__ A,
    int F, int K, int N, int Pu, int ud, int Srin, int tid)
{
    const int total = N * F;
    float accl[8];
    int cnt = 0;
    for (int o = tid; o < total; o += NT) {
        int n = o / F;
        int m = o - n * F;
        int dp = m / Pu;
        int ur = m - dp * Pu;
        int inb = dp * ud * Pu + ur;
        float s = 0.f;
        for (int k = 0; k < K; ++k) {
            int rin = k / ud;
            int u = k - rin * ud;
            s = fmaf(W[inb + rin * Srin + u * Pu], A[k * N + n], s);
        }
        accl[cnt++] = s;
    }
    __syncthreads();
    cnt = 0;
    for (int o = tid; o < total; o += NT) {
        int n = o / F;
        int m = o - n * F;
        W[n * F + m] = accl[cnt++];
    }
    __syncthreads();
}

// Interior rows, steps 0..4: F=1024, N=16, Pu = 1<<PSH >= 4.
// g = tid>>8 picks 8 n's, t = tid&255 picks m-vec 4t..4t+3 (2 m-pair packs).
// acc[n(8)][m-pair(2)]. A2 holds pre-duplicated (a,a) u64 pairs; per k:
// 1 x LDS.128 + 4 broadcast A2 LDS.128 + 16 FFMA2, no movs.
template <int K, int PSH>
__device__ __forceinline__ void step_fast_vec(
    float* __restrict__ W, const u64* __restrict__ A2, int tid)
{
    const int g = tid >> 8;           // n-group: n = 8g..8g+7
    const int t = tid & 255;
    const int mb = t << 2;            // m-vec base
    const int dp = mb >> PSH;
    const int ur = mb & ((1 << PSH) - 1);
    const int inb = (dp << (PSH + 2)) + ur;

    u64 acc[8][2];
#pragma unroll
    for (int n = 0; n < 8; ++n) { acc[n][0] = 0ull; acc[n][1] = 0ull; }

#pragma unroll
    for (int k = 0; k < K; ++k) {
        const int off = (k >> 2) * 4096 + ((k & 3) << PSH);
        const ulonglong2 xv = *(const ulonglong2*)(W + inb + off);
        const ulonglong2 a01 = *(const ulonglong2*)(A2 + k * 16 + g * 8);
        const ulonglong2 a23 = *(const ulonglong2*)(A2 + k * 16 + g * 8 + 2);
        const ulonglong2 a45 = *(const ulonglong2*)(A2 + k * 16 + g * 8 + 4);
        const ulonglong2 a67 = *(const ulonglong2*)(A2 + k * 16 + g * 8 + 6);
        const u64 ap[8] = { a01.x, a01.y, a23.x, a23.y,
                            a45.x, a45.y, a67.x, a67.y };
#pragma unroll
        for (int n = 0; n < 8; ++n) {
            fma2(acc[n][0], xv.x, ap[n]);
            fma2(acc[n][1], xv.y, ap[n]);
        }
    }

    __syncthreads();
#pragma unroll
    for (int n = 0; n < 8; ++n) {
        ulonglong2 o;
        o.x = acc[n][0];
        o.y = acc[n][1];
        *(ulonglong2*)(W + (g * 8 + n) * 1024 + mb) = o;
    }
    __syncthreads();
}

// Interior rows, step 5: F=1024, N=4, K=16 (input layout rin*4096 + m*4 + u).
// 512 threads, 2 m each; acc packed over n-pairs (plain A, pairs contiguous).
__device__ __forceinline__ void step_fast_last(
    float* __restrict__ W, const float* __restrict__ A, int tid)
{
    const int m0 = tid * 2;
    u64 acc[2][2];                    // [m-slot][n-pair]
    acc[0][0] = acc[0][1] = acc[1][0] = acc[1][1] = 0ull;

#pragma unroll
    for (int rin = 0; rin < 4; ++rin) {
        const float4 xv0 = *(const float4*)(W + m0 * 4 + rin * 4096);
        const float4 xv1 = *(const float4*)(W + (m0 + 1) * 4 + rin * 4096);
#pragma unroll
        for (int u = 0; u < 4; ++u) {
            const float x0 = (u == 0) ? xv0.x : (u == 1) ? xv0.y : (u == 2) ? xv0.z : xv0.w;
            const float x1 = (u == 0) ? xv1.x : (u == 1) ? xv1.y : (u == 2) ? xv1.z : xv1.w;
            const ulonglong2 a2 = *(const ulonglong2*)(A + (rin * 4 + u) * 4);
            const u64 p0 = pk(x0);
            const u64 p1 = pk(x1);
            fma2(acc[0][0], p0, a2.x);
            fma2(acc[0][1], p0, a2.y);
            fma2(acc[1][0], p1, a2.x);
            fma2(acc[1][1], p1, a2.y);
        }
    }
    __syncthreads();
#pragma unroll
    for (int p = 0; p < 2; ++p) {
        const float2 v01 = upk(acc[p][0]);
        const float2 v23 = upk(acc[p][1]);
        W[0 * 1024 + m0 + p] = v01.x;
        W[1 * 1024 + m0 + p] = v01.y;
        W[2 * 1024 + m0 + p] = v23.x;
        W[3 * 1024 + m0 + p] = v23.y;
    }
    __syncthreads();
}

__global__ __launch_bounds__(NT, 2)
void peps_amp_kernel(const int* __restrict__ x, const float* __restrict__ T,
                     float* __restrict__ out)
{
    extern __shared__ float smem[];
    float* W = smem;                              // [0, 16384)
    u64* A2 = (u64*)(smem + 16384);               // 6*256 u64 = 3072 floats
    float* As = smem + 16384 + 3072;              // 6*256 floats
    int* spins = (int*)(smem + 16384 + 3072 + 1536);  // 36 (+ pad)

    const int b = blockIdx.x;
    const int tid = threadIdx.x;

    if (tid < 36) spins[tid] = x[b * 36 + tid];
    if (tid == 0) W[0] = 1.0f;
    __syncthreads();

    for (int i = 0; i < 6; ++i) {
        const int ud = (i == 0) ? 1 : 4;
        const int dd = (i == 5) ? 1 : 4;
        const bool l2r = ((i & 1) == 0);

        // Stage this row's 6 site matrices: As[st][k*N + n],
        // k = rin*ud + u, n = rout*dd + d.
        for (int st = 0; st < 6; ++st) {
            const int Rin  = (st == 0) ? 1 : 4;
            const int Rout = (st == 5) ? 1 : 4;
            const int K = ud * Rin;
            const int N = Rout * dd;
            const int jc = l2r ? st : (5 - st);
            const int s = spins[i * 6 + jc];
            const float* Tb = T + (size_t)((i * 6 + jc) * 2 + s) * 256;
            for (int idx = tid; idx < K * N; idx += NT) {
                int k = idx / N, n = idx - k * N;
                int rin = k / ud, u = k - rin * ud;
                int rout = n / dd, d = n - rout * dd;
                int r = l2r ? rout : rin;
                int l = l2r ? rin : rout;
                As[st * 256 + idx] = Tb[u * 64 + r * 16 + d * 4 + l];
            }
        }
        __syncthreads();

        // Interior rows: pre-duplicate A into (a,a) u64 pairs for the hot loop.
        if (ud == 4 && dd == 4) {
            for (int idx = tid; idx < 6 * 256; idx += NT)
                A2[idx] = pk(As[idx]);
            __syncthreads();
        }

        for (int st = 0; st < 6; ++st) {
            const float* A = As + st * 256;

            if (ud == 4 && dd == 4) {
                switch (st) {
                    case 0: step_fast_vec<4, 10>(W, A2 + st * 256, tid); break;
                    case 1: step_fast_vec<16, 8>(W, A2 + st * 256, tid); break;
                    case 2: step_fast_vec<16, 6>(W, A2 + st * 256, tid); break;
                    case 3: step_fast_vec<16, 4>(W, A2 + st * 256, tid); break;
                    case 4: step_fast_vec<16, 2>(W, A2 + st * 256, tid); break;
                    default: step_fast_last(W, A, tid); break;
                }
            } else {
                const int Rin  = (st == 0) ? 1 : 4;
                const int Rout = (st == 5) ? 1 : 4;
                const int K = ud * Rin;
                const int N = Rout * dd;
                const int Pd = (dd == 1) ? 1 : (1 << (2 * st));
                const int Pu = (ud == 1) ? 1 : (1 << (2 * (5 - st)));
                step_generic(W, A, Pd * Pu, K, N, Pu, ud,
                             Pd * ud * Pu, tid);
            }
        }
    }

    if (tid == 0) out[b] = W[0];
}

extern "C" void kernel_launch(void* const* d_in, const int* in_sizes, int n_in,
                              void* d_out, int out_size)
{
    const int T_ELEMS = 6 * 6 * 2 * 4 * 4 * 4 * 4;   // 73728
    const int* x;
    const float* T;
    if (in_sizes[0] == T_ELEMS) {
        T = (const float*)d_in[0];
        x = (const int*)d_in[1];
    } else {
        x = (const int*)d_in[0];
        T = (const float*)d_in[1];
    }

    const int smem_bytes = (16384 + 3072 + 1536 + 64) * (int)sizeof(float);
    cudaFuncSetAttribute(peps_amp_kernel,
                         cudaFuncAttributeMaxDynamicSharedMemorySize, smem_bytes);
    cudaFuncSetAttribute(peps_amp_kernel,
                         cudaFuncAttributePreferredSharedMemoryCarveout, 100);

    peps_amp_kernel<<<out_size, NT, smem_bytes>>>(x, T, (float*)d_out);
}

// round 8
// speedup vs baseline: 2.9642x; 1.4034x over previous
#include <cuda_runtime.h>
#include <cuda_bf16.h>

// PEPS 6x6, D=4, phys=2, batch=1024. Row-sweep exact contraction, snake order.
// One CTA (512 threads) per config, single W buffer, 2 CTAs/SM.
// Interior inner loop identical to the proven round-4 version (fma.rn.f32x2,
// acc packed over m-pairs, A broadcast loads + dup movs on the idle ALU pipe).
// Boundary rows fully templated (no runtime div/mod); all 36 site matrices
// staged up-front (one staging pass, one barrier).

#define NT 512

typedef unsigned long long u64;

__device__ __forceinline__ u64 pk(float v) {
    u64 r;
    asm("mov.b64 %0, {%1, %1};" : "=l"(r) : "f"(v));
    return r;
}
__device__ __forceinline__ void fma2(u64& d, u64 a, u64 b) {
    asm("fma.rn.f32x2 %0, %1, %2, %0;" : "+l"(d) : "l"(a), "l"(b));
}
__device__ __forceinline__ float2 upk(u64 v) {
    float2 r;
    asm("mov.b64 {%0, %1}, %2;" : "=f"(r.x), "=f"(r.y) : "l"(v));
    return r;
}

// Boundary-row step, all shape parameters compile-time (divs become shifts).
template <int F, int K, int N, int PU, int UD, int SRIN>
__device__ __forceinline__ void step_b(
    float* __restrict__ W, const float* __restrict__ A, int tid)
{
    constexpr int TOTAL = N * F;
    constexpr int NOUT = (TOTAL + NT - 1) / NT;
    float accl[NOUT];
    int cnt = 0;
    for (int o = tid; o < TOTAL; o += NT) {
        const int n = o / F;
        const int m = o - n * F;
        const int dp = m / PU;
        const int ur = m - dp * PU;
        const int inb = dp * UD * PU + ur;
        float s = 0.f;
#pragma unroll
        for (int k = 0; k < K; ++k) {
            const int rin = k / UD;
            const int u = k - rin * UD;
            s = fmaf(W[inb + rin * SRIN + u * PU], A[k * N + n], s);
        }
        accl[cnt++] = s;
    }
    __syncthreads();
    cnt = 0;
    for (int o = tid; o < TOTAL; o += NT) {
        const int n = o / F;
        const int m = o - n * F;
        W[n * F + m] = accl[cnt++];
    }
    __syncthreads();
}

// Interior rows, steps 0..4 (round-4 proven codegen): F=1024, N=16,
// Pu = 1<<PSH >= 4. g = tid>>8 picks 8 n's, t = tid&255 picks m-vec 4t..4t+3
// (2 m-pair packs). Per k: 1 LDS.128 x + 2 broadcast LDS.128 A + 8 pk movs
// (ALU pipe) + 16 FFMA2.
template <int K, int PSH>
__device__ __forceinline__ void step_fast_vec(
    float* __restrict__ W, const float* __restrict__ A, int tid)
{
    const int g = tid >> 8;           // n-group: n = 8g..8g+7
    const int t = tid & 255;
    const int mb = t << 2;            // m-vec base
    const int dp = mb >> PSH;
    const int ur = mb & ((1 << PSH) - 1);
    const int inb = (dp << (PSH + 2)) + ur;

    u64 acc[8][2];
#pragma unroll
    for (int n = 0; n < 8; ++n) { acc[n][0] = 0ull; acc[n][1] = 0ull; }

#pragma unroll
    for (int k = 0; k < K; ++k) {
        const int off = (k >> 2) * 4096 + ((k & 3) << PSH);
        const ulonglong2 xv = *(const ulonglong2*)(W + inb + off);
        const float4 alo = *(const float4*)(A + k * 16 + g * 8);
        const float4 ahi = *(const float4*)(A + k * 16 + g * 8 + 4);
        const float av[8] = { alo.x, alo.y, alo.z, alo.w,
                              ahi.x, ahi.y, ahi.z, ahi.w };
#pragma unroll
        for (int n = 0; n < 8; ++n) {
            const u64 a2 = pk(av[n]);
            fma2(acc[n][0], xv.x, a2);
            fma2(acc[n][1], xv.y, a2);
        }
    }

    __syncthreads();
#pragma unroll
    for (int n = 0; n < 8; ++n) {
        ulonglong2 o;
        o.x = acc[n][0];
        o.y = acc[n][1];
        *(ulonglong2*)(W + (g * 8 + n) * 1024 + mb) = o;
    }
    __syncthreads();
}

// Interior rows, step 5: F=1024, N=4, K=16 (input layout rin*4096 + m*4 + u).
// 512 threads, 2 m each; acc packed over n-pairs.
__device__ __forceinline__ void step_fast_last(
    float* __restrict__ W, const float* __restrict__ A, int tid)
{
    const int m0 = tid * 2;
    u64 acc[2][2];                    // [m-slot][n-pair]
    acc[0][0] = acc[0][1] = acc[1][0] = acc[1][1] = 0ull;

#pragma unroll
    for (int rin = 0; rin < 4; ++rin) {
        const float4 xv0 = *(const float4*)(W + m0 * 4 + rin * 4096);
        const float4 xv1 = *(const float4*)(W + (m0 + 1) * 4 + rin * 4096);
#pragma unroll
        for (int u = 0; u < 4; ++u) {
            const float x0 = (u == 0) ? xv0.x : (u == 1) ? xv0.y : (u == 2) ? xv0.z : xv0.w;
            const float x1 = (u == 0) ? xv1.x : (u == 1) ? xv1.y : (u == 2) ? xv1.z : xv1.w;
            const ulonglong2 a2 = *(const ulonglong2*)(A + (rin * 4 + u) * 4);
            const u64 p0 = pk(x0);
            const u64 p1 = pk(x1);
            fma2(acc[0][0], p0, a2.x);
            fma2(acc[0][1], p0, a2.y);
            fma2(acc[1][0], p1, a2.x);
            fma2(acc[1][1], p1, a2.y);
        }
    }
    __syncthreads();
#pragma unroll
    for (int p = 0; p < 2; ++p) {
        const float2 v01 = upk(acc[p][0]);
        const float2 v23 = upk(acc[p][1]);
        W[0 * 1024 + m0 + p] = v01.x;
        W[1 * 1024 + m0 + p] = v01.y;
        W[2 * 1024 + m0 + p] = v23.x;
        W[3 * 1024 + m0 + p] = v23.y;
    }
    __syncthreads();
}

__global__ __launch_bounds__(NT, 2)
void peps_amp_kernel(const int* __restrict__ x, const float* __restrict__ T,
                     float* __restrict__ out)
{
    extern __shared__ float smem[];
    float* W = smem;                               // [0, 16384)
    float* As = smem + 16384;                      // 36 * 256 = 9216 floats
    int* spins = (int*)(smem + 16384 + 9216);      // 36 (+ pad)

    const int b = blockIdx.x;
    const int tid = threadIdx.x;

    if (tid < 36) spins[tid] = x[b * 36 + tid];
    if (tid == 0) W[0] = 1.0f;
    __syncthreads();

    // Stage ALL 36 site matrices once: As[(i*6+st)*256 + k*N + n],
    // k = rin*ud + u, n = rout*dd + d.  L->R rows: in=left, out=right;
    // R->L rows: in=right, out=left.
    for (int site = tid; site < 36 * 8; site += NT) {
        // 288 chunks of 32 elements each (max K*N = 256 -> 8 chunks/site)
        const int sidx = site >> 3;
        const int chunk = site & 7;
        const int i = sidx / 6;
        const int st = sidx - i * 6;
        const int ud = (i == 0) ? 1 : 4;
        const int dd = (i == 5) ? 1 : 4;
        const bool l2r = ((i & 1) == 0);
        const int Rin  = (st == 0) ? 1 : 4;
        const int Rout = (st == 5) ? 1 : 4;
        const int K = ud * Rin;
        const int N = Rout * dd;
        const int jc = l2r ? st : (5 - st);
        const int s = spins[i * 6 + jc];
        const float* Tb = T + (size_t)((i * 6 + jc) * 2 + s) * 256;
        const int kn = K * N;
        for (int idx = chunk * 32; idx < min(kn, chunk * 32 + 32); ++idx) {
            int k = idx / N, n = idx - k * N;
            int rin = k / ud, u = k - rin * ud;
            int rout = n / dd, d = n - rout * dd;
            int r = l2r ? rout : rin;
            int l = l2r ? rin : rout;
            As[sidx * 256 + idx] = Tb[u * 64 + r * 16 + d * 4 + l];
        }
    }
    __syncthreads();

    // ---- Row 0 (ud=1, dd=4, L->R) ----
    {
        const float* A = As;
        step_b<1,    1, 16, 1, 1, 1   >(W, A + 0 * 256, tid);
        step_b<4,    4, 16, 1, 1, 4   >(W, A + 1 * 256, tid);
        step_b<16,   4, 16, 1, 1, 16  >(W, A + 2 * 256, tid);
        step_b<64,   4, 16, 1, 1, 64  >(W, A + 3 * 256, tid);
        step_b<256,  4, 16, 1, 1, 256 >(W, A + 4 * 256, tid);
        step_b<1024, 4, 4,  1, 1, 1024>(W, A + 5 * 256, tid);
    }

    // ---- Rows 1..4 (interior) ----
    for (int i = 1; i <= 4; ++i) {
        const float* A = As + i * 6 * 256;
        step_fast_vec<4, 10>(W, A + 0 * 256, tid);
        step_fast_vec<16, 8>(W, A + 1 * 256, tid);
        step_fast_vec<16, 6>(W, A + 2 * 256, tid);
        step_fast_vec<16, 4>(W, A + 3 * 256, tid);
        step_fast_vec<16, 2>(W, A + 4 * 256, tid);
        step_fast_last(W, A + 5 * 256, tid);
    }

    // ---- Row 5 (ud=4, dd=1, R->L) ----
    {
        const float* A = As + 5 * 6 * 256;
        step_b<1024, 4,  4, 1024, 4, 4096>(W, A + 0 * 256, tid);
        step_b<256, 16,  4, 256,  4, 1024>(W, A + 1 * 256, tid);
        step_b<64,  16,  4, 64,   4, 256 >(W, A + 2 * 256, tid);
        step_b<16,  16,  4, 16,   4, 64  >(W, A + 3 * 256, tid);
        step_b<4,   16,  4, 4,    4, 16  >(W, A + 4 * 256, tid);
        step_b<1,   16,  1, 1,    4, 4   >(W, A + 5 * 256, tid);
    }

    if (tid == 0) out[b] = W[0];
}

extern "C" void kernel_launch(void* const* d_in, const int* in_sizes, int n_in,
                              void* d_out, int out_size)
{
    const int T_ELEMS = 6 * 6 * 2 * 4 * 4 * 4 * 4;   // 73728
    const int* x;
    const float* T;
    if (in_sizes[0] == T_ELEMS) {
        T = (const float*)d_in[0];
        x = (const int*)d_in[1];
    } else {
        x = (const int*)d_in[0];
        T = (const float*)d_in[1];
    }

    const int smem_bytes = (16384 + 9216 + 64) * (int)sizeof(float);
    cudaFuncSetAttribute(peps_amp_kernel,
                         cudaFuncAttributeMaxDynamicSharedMemorySize, smem_bytes);
    cudaFuncSetAttribute(peps_amp_kernel,
                         cudaFuncAttributePreferredSharedMemoryCarveout, 100);

    peps_amp_kernel<<<out_size, NT, smem_bytes>>>(x, T, (float*)d_out);
}